// round 14
// baseline (speedup 1.0000x reference)
#include <cuda_runtime.h>
#include <cstdint>

#define N_POS   4096
#define HEADS   4
#define DHEAD   32
#define C_IN    256
#define HID     128          // HEADS*DHEAD
#define BATCH   4
#define SCALE   10.0f

// Scratch (no cudaMalloc allowed): qkv [b][3*128][n], attn-out [b][128][n]
__device__ float g_qkv[(size_t)BATCH * 3 * HID * N_POS];   // 25.2 MB
__device__ float g_att[(size_t)BATCH * HID * N_POS];       //  8.4 MB

#define FULLM  0xffffffffu

__device__ __forceinline__ uint32_t f2tf(float x) {
    uint32_t r;
    asm("cvt.rna.tf32.f32 %0, %1;" : "=r"(r) : "f"(x));
    return r;
}

// pack two fp32 into half2: lo -> low half, hi -> high half
__device__ __forceinline__ uint32_t pack_h2(float lo, float hi) {
    uint32_t r;
    asm("cvt.rn.f16x2.f32 %0, %1, %2;" : "=r"(r) : "f"(hi), "f"(lo));
    return r;
}

__device__ __forceinline__ void mma_tf32(float d[4], const uint32_t a[4],
                                         const uint32_t b[2]) {
    asm volatile(
        "mma.sync.aligned.m16n8k8.row.col.f32.tf32.tf32.f32 "
        "{%0,%1,%2,%3}, {%4,%5,%6,%7}, {%8,%9}, {%0,%1,%2,%3};"
        : "+f"(d[0]), "+f"(d[1]), "+f"(d[2]), "+f"(d[3])
        : "r"(a[0]), "r"(a[1]), "r"(a[2]), "r"(a[3]), "r"(b[0]), "r"(b[1]));
}

__device__ __forceinline__ void mma_f16(float d[4], const uint32_t a[4],
                                        const uint32_t b[2]) {
    asm volatile(
        "mma.sync.aligned.m16n8k16.row.col.f32.f16.f16.f32 "
        "{%0,%1,%2,%3}, {%4,%5,%6,%7}, {%8,%9}, {%0,%1,%2,%3};"
        : "+f"(d[0]), "+f"(d[1]), "+f"(d[2]), "+f"(d[3])
        : "r"(a[0]), "r"(a[1]), "r"(a[2]), "r"(a[3]), "r"(b[0]), "r"(b[1]));
}

__device__ __forceinline__ void cp_async16(void* smem_dst, const void* gsrc) {
    uint32_t s = (uint32_t)__cvta_generic_to_shared(smem_dst);
    asm volatile("cp.async.cg.shared.global [%0], [%1], 16;\n"
                 :: "r"(s), "l"(gsrc) : "memory");
}

// ---------------------------------------------------------------------------
// Projection GEMM (round-12 measured-best version): tensor-core, 3-term tf32
// split done once at staging into separate hi/lo arrays, register
// double-buffer prefetch, one sync per k-tile. Optional fused L2-norm.
// ---------------------------------------------------------------------------
#define WS_STR 20
#define XS_STR 72

template <bool DO_NORM>
__device__ __forceinline__ void gemm_tc_body(
    const float* __restrict__ W, const float* __restrict__ X,
    float* __restrict__ Y, const float* __restrict__ bias,
    int K, long xstride_b, long ystride_b)
{
    __shared__ uint32_t WsH[2][64 * WS_STR], WsL[2][64 * WS_STR];
    __shared__ uint32_t XsH[2][16 * XS_STR], XsL[2][16 * XS_STR];
    __shared__ float nrm[128];            // [group 0..1][col 0..63]

    const int b  = blockIdx.z;
    const int o0 = blockIdx.y * 64;
    const int i0 = blockIdx.x * 64;
    const float* Xb = X + (long)b * xstride_b;
    float*       Yb = Y + (long)b * ystride_b;

    const int tid  = threadIdx.x;
    const int wid  = tid >> 5;
    const int lane = tid & 31;
    const int gid  = lane >> 2;
    const int tig  = lane & 3;
    const int wq   = wid >> 1;
    const int wn   = wid & 1;

    const int wo = tid >> 2;              // staging: W row (0..63)
    const int wc = (tid & 3) * 4;         // staging: W col group
    const int xc = tid >> 4;              // staging: X row (0..15)
    const int xi = (tid & 15) * 4;        // staging: X col group

    const int KT = K / 16;

    float4 wreg, xreg;

    auto stage_split = [&](int s) {
        uint4 h, l;
        h.x = f2tf(wreg.x); l.x = f2tf(wreg.x - __uint_as_float(h.x));
        h.y = f2tf(wreg.y); l.y = f2tf(wreg.y - __uint_as_float(h.y));
        h.z = f2tf(wreg.z); l.z = f2tf(wreg.z - __uint_as_float(h.z));
        h.w = f2tf(wreg.w); l.w = f2tf(wreg.w - __uint_as_float(h.w));
        *(uint4*)&WsH[s][wo * WS_STR + wc] = h;
        *(uint4*)&WsL[s][wo * WS_STR + wc] = l;
        h.x = f2tf(xreg.x); l.x = f2tf(xreg.x - __uint_as_float(h.x));
        h.y = f2tf(xreg.y); l.y = f2tf(xreg.y - __uint_as_float(h.y));
        h.z = f2tf(xreg.z); l.z = f2tf(xreg.z - __uint_as_float(h.z));
        h.w = f2tf(xreg.w); l.w = f2tf(xreg.w - __uint_as_float(h.w));
        *(uint4*)&XsH[s][xc * XS_STR + xi] = h;
        *(uint4*)&XsL[s][xc * XS_STR + xi] = l;
    };
    auto load_tile = [&](int kt) {
        const int k0 = kt * 16;
        wreg = *(const float4*)&W[(long)(o0 + wo) * K + k0 + wc];
        xreg = *(const float4*)&Xb[(long)(k0 + xc) * N_POS + i0 + xi];
    };

    // prologue: tile 0 staged, tile 1 in regs
    load_tile(0);
    stage_split(0);
    if (KT > 1) load_tile(1);
    if (DO_NORM && tid < 128) nrm[tid] = 0.0f;
    __syncthreads();

    float acc[4][4] = {};

    for (int kt = 0; kt < KT; kt++) {
        const int s = kt & 1;
        if (kt + 1 < KT) {
            stage_split(s ^ 1);               // STS tile kt+1 (regs -> smem)
            if (kt + 2 < KT) load_tile(kt + 2);  // LDG tile kt+2 -> regs
        }

        #pragma unroll
        for (int kk = 0; kk < 2; kk++) {
            const int ar = wq * 16 + gid;
            const int ac = kk * 8 + tig;
            uint32_t aH[4], aL[4];
            aH[0] = WsH[s][ar * WS_STR + ac];
            aH[1] = WsH[s][(ar + 8) * WS_STR + ac];
            aH[2] = WsH[s][ar * WS_STR + ac + 4];
            aH[3] = WsH[s][(ar + 8) * WS_STR + ac + 4];
            aL[0] = WsL[s][ar * WS_STR + ac];
            aL[1] = WsL[s][(ar + 8) * WS_STR + ac];
            aL[2] = WsL[s][ar * WS_STR + ac + 4];
            aL[3] = WsL[s][(ar + 8) * WS_STR + ac + 4];
            #pragma unroll
            for (int nt = 0; nt < 4; nt++) {
                const int col = wn * 32 + nt * 8 + gid;
                const int cr  = kk * 8 + tig;
                uint32_t bH[2], bL[2];
                bH[0] = XsH[s][cr * XS_STR + col];
                bH[1] = XsH[s][(cr + 4) * XS_STR + col];
                bL[0] = XsL[s][cr * XS_STR + col];
                bL[1] = XsL[s][(cr + 4) * XS_STR + col];
                mma_tf32(acc[nt], aH, bH);
                mma_tf32(acc[nt], aH, bL);
                mma_tf32(acc[nt], aL, bH);
            }
        }
        __syncthreads();
    }

    if (DO_NORM && o0 < 2 * HID) {
        // fused L2-norm: sum of squares over each 32-row (d) group, per column
        const int g = wq >> 1;
        float p0[4], p1[4];
        #pragma unroll
        for (int nt = 0; nt < 4; nt++) {
            p0[nt] = acc[nt][0] * acc[nt][0] + acc[nt][2] * acc[nt][2];
            p1[nt] = acc[nt][1] * acc[nt][1] + acc[nt][3] * acc[nt][3];
            #pragma unroll
            for (int m = 4; m < 32; m <<= 1) {
                p0[nt] += __shfl_xor_sync(FULLM, p0[nt], m);
                p1[nt] += __shfl_xor_sync(FULLM, p1[nt], m);
            }
        }
        if (lane < 4) {
            #pragma unroll
            for (int nt = 0; nt < 4; nt++) {
                const int col = wn * 32 + nt * 8 + 2 * tig;
                atomicAdd(&nrm[g * 64 + col],     p0[nt]);
                atomicAdd(&nrm[g * 64 + col + 1], p1[nt]);
            }
        }
        __syncthreads();
        #pragma unroll
        for (int nt = 0; nt < 4; nt++) {
            const int col = wn * 32 + nt * 8 + 2 * tig;
            float i0v = 1.0f / fmaxf(sqrtf(nrm[g * 64 + col]),     1e-12f);
            float i1v = 1.0f / fmaxf(sqrtf(nrm[g * 64 + col + 1]), 1e-12f);
            acc[nt][0] *= i0v; acc[nt][2] *= i0v;
            acc[nt][1] *= i1v; acc[nt][3] *= i1v;
        }
    }

    const int orow = o0 + wq * 16 + gid;
    const float b0 = bias ? bias[orow]     : 0.0f;
    const float b1 = bias ? bias[orow + 8] : 0.0f;
    #pragma unroll
    for (int nt = 0; nt < 4; nt++) {
        const int col = i0 + wn * 32 + nt * 8 + 2 * tig;
        float2 lo, hi;
        lo.x = acc[nt][0] + b0; lo.y = acc[nt][1] + b0;
        hi.x = acc[nt][2] + b1; hi.y = acc[nt][3] + b1;
        *(float2*)&Yb[(long)orow * N_POS + col]       = lo;
        *(float2*)&Yb[(long)(orow + 8) * N_POS + col] = hi;
    }
}

__global__ __launch_bounds__(256) void gemm_qkv_kernel(
    const float* __restrict__ W, const float* __restrict__ X)
{
    gemm_tc_body<true>(W, X, g_qkv, nullptr, C_IN,
                       (long)C_IN * N_POS, (long)3 * HID * N_POS);
}

__global__ __launch_bounds__(256) void gemm_out_kernel(
    const float* __restrict__ W, float* __restrict__ Y,
    const float* __restrict__ bias)
{
    gemm_tc_body<false>(W, g_att, Y, bias, HID,
                        (long)HID * N_POS, (long)C_IN * N_POS);
}

// ---------------------------------------------------------------------------
// Tensor-core flash attention, BOTH GEMMs fp16 m16n8k16 (fp32 accumulate).
//  fp16 mantissa == tf32 mantissa (10 bits) and q,k in [-1,1] -> fp16 QK'
//  has identical precision to the former tf32 path at half the MMA count.
//  Softmax: p = exp(10*s), no shift (p in [e-10, e10], fp16-normal range).
//  GEMM2: S C-frag IS the fp16 A-frag layout -> P packs with cvt only.
//  K/V staged fp32 via 2-stage cp.async ring (wait_group 1, refill at end).
//  KS_STR=68: GEMM1 b-frag banks (8*tig+gid+8*nt) mod 32 conflict-free.
// Block = (b, h, 128-query tile), 8 warps (wq 0..3 x wn 0..1), 512 blocks.
// ---------------------------------------------------------------------------
#define KS_STR 68
#define VS_STR 68
#define OS_STR 136
#define PB_STR 33
#define STG_WORDS (32 * KS_STR + 32 * VS_STR)   // 4352 floats per stage

__global__ __launch_bounds__(256, 2) void attn_tc_kernel()
{
    __shared__ float SB[2 * STG_WORDS];   // K/V ring; aliased by epilogue
    __shared__ float sh_l[128];

    const int b   = blockIdx.z;
    const int h   = blockIdx.y;
    const int q0  = blockIdx.x * 128;
    const int tid = threadIdx.x;
    const int wid  = tid >> 5;
    const int lane = tid & 31;
    const int gid  = lane >> 2;
    const int tig  = lane & 3;
    const int wq   = wid >> 1;   // 0..3 : 32-row q group
    const int wn   = wid & 1;    // 0..1 : j/k half

    const float* qb = g_qkv + ((long)(b * 3 + 0) * HID + h * DHEAD) * N_POS;
    const float* kb = g_qkv + ((long)(b * 3 + 1) * HID + h * DHEAD) * N_POS;
    const float* vb = g_qkv + ((long)(b * 3 + 2) * HID + h * DHEAD) * N_POS;

    float* Ks0 = SB;
    float* Vs0 = SB + 32 * KS_STR;
    float* Ks1 = SB + STG_WORDS;
    float* Vs1 = SB + STG_WORDS + 32 * KS_STR;

    // ---- stage tiles 0 and 1 ----
    #pragma unroll
    for (int r = 0; r < 2; r++) {
        int c = tid + r * 256;
        int d = c >> 4, j4 = (c & 15) * 4;
        cp_async16(Ks0 + d * KS_STR + j4, kb + (long)d * N_POS + j4);
        cp_async16(Vs0 + d * VS_STR + j4, vb + (long)d * N_POS + j4);
    }
    asm volatile("cp.async.commit_group;\n" ::: "memory");
    #pragma unroll
    for (int r = 0; r < 2; r++) {
        int c = tid + r * 256;
        int d = c >> 4, j4 = (c & 15) * 4;
        cp_async16(Ks1 + d * KS_STR + j4, kb + (long)d * N_POS + 64 + j4);
        cp_async16(Vs1 + d * VS_STR + j4, vb + (long)d * N_POS + 64 + j4);
    }
    asm volatile("cp.async.commit_group;\n" ::: "memory");

    // ---- Q fragments in registers as fp16 (one-time) ----
    // fp16 A-frag (m16n8k16): a0=(row gid, d 2tig..2tig+1), a1=(row+8, same),
    //                         a2=(row gid, d 2tig+8..9),    a3=(row+8, same)
    uint32_t qf[2][2][4];   // [mt][kk2: d-half]
    #pragma unroll
    for (int mt = 0; mt < 2; mt++) {
        const int row = wq * 32 + mt * 16 + gid;
        const float* qp = qb + q0 + row;
        #pragma unroll
        for (int kk2 = 0; kk2 < 2; kk2++) {
            const int d0 = kk2 * 16 + 2 * tig;
            qf[mt][kk2][0] = pack_h2(qp[(long)d0 * N_POS],
                                     qp[(long)(d0 + 1) * N_POS]);
            qf[mt][kk2][1] = pack_h2(qp[(long)d0 * N_POS + 8],
                                     qp[(long)(d0 + 1) * N_POS + 8]);
            qf[mt][kk2][2] = pack_h2(qp[(long)(d0 + 8) * N_POS],
                                     qp[(long)(d0 + 9) * N_POS]);
            qf[mt][kk2][3] = pack_h2(qp[(long)(d0 + 8) * N_POS + 8],
                                     qp[(long)(d0 + 9) * N_POS + 8]);
        }
    }
    if (tid < 128) sh_l[tid] = 0.0f;

    float O[2][4][4] = {};
    float l_lo[2] = {}, l_hi[2] = {};

    for (int it = 0; it < N_POS / 64; it++) {
        const int s = it & 1;
        float* KsS = s ? Ks1 : Ks0;
        float* VsS = s ? Vs1 : Vs0;

        asm volatile("cp.async.wait_group 1;\n" ::: "memory");
        __syncthreads();   // tile it visible to all; also fences Q/sh_l init

        // ---- GEMM1: S[32q x 32j] = Q K'  (fp16 m16n8k16) ----
        float S[2][4][4] = {};
        #pragma unroll
        for (int kk2 = 0; kk2 < 2; kk2++) {
            const int d0 = kk2 * 16 + 2 * tig;
            #pragma unroll
            for (int nt = 0; nt < 4; nt++) {
                const int col = wn * 32 + nt * 8 + gid;
                uint32_t bb[2];
                bb[0] = pack_h2(KsS[(long)d0 * KS_STR + col],
                                KsS[(long)(d0 + 1) * KS_STR + col]);
                bb[1] = pack_h2(KsS[(long)(d0 + 8) * KS_STR + col],
                                KsS[(long)(d0 + 9) * KS_STR + col]);
                mma_f16(S[0][nt], qf[0][kk2], bb);
                mma_f16(S[1][nt], qf[1][kk2], bb);
            }
        }

        // ---- P = exp(10*s) (no shift); accumulate l ----
        #pragma unroll
        for (int mt = 0; mt < 2; mt++)
            #pragma unroll
            for (int nt = 0; nt < 4; nt++) {
                S[mt][nt][0] = __expf(S[mt][nt][0] * SCALE);
                S[mt][nt][1] = __expf(S[mt][nt][1] * SCALE);
                S[mt][nt][2] = __expf(S[mt][nt][2] * SCALE);
                S[mt][nt][3] = __expf(S[mt][nt][3] * SCALE);
                l_lo[mt] += S[mt][nt][0] + S[mt][nt][1];
                l_hi[mt] += S[mt][nt][2] + S[mt][nt][3];
            }

        // ---- GEMM2: O += P V'  (fp16 m16n8k16, no shuffles) ----
        #pragma unroll
        for (int kk2 = 0; kk2 < 2; kk2++) {
            const int g = kk2 * 2;
            uint32_t a0[4], a1[4];
            a0[0] = pack_h2(S[0][g][0],     S[0][g][1]);
            a0[1] = pack_h2(S[0][g][2],     S[0][g][3]);
            a0[2] = pack_h2(S[0][g + 1][0], S[0][g + 1][1]);
            a0[3] = pack_h2(S[0][g + 1][2], S[0][g + 1][3]);
            a1[0] = pack_h2(S[1][g][0],     S[1][g][1]);
            a1[1] = pack_h2(S[1][g][2],     S[1][g][3]);
            a1[2] = pack_h2(S[1][g + 1][0], S[1][g + 1][1]);
            a1[3] = pack_h2(S[1][g + 1][2], S[1][g + 1][3]);
            const int kbase = wn * 32 + kk2 * 16;
            #pragma unroll
            for (int dt = 0; dt < 4; dt++) {
                const int dcol = dt * 8 + gid;
                float2 v0 = *(const float2*)&VsS[dcol * VS_STR + kbase + 2 * tig];
                float2 v1 = *(const float2*)&VsS[dcol * VS_STR + kbase + 2 * tig + 8];
                uint32_t bb[2];
                bb[0] = pack_h2(v0.x, v0.y);
                bb[1] = pack_h2(v1.x, v1.y);
                mma_f16(O[0][dt], a0, bb);
                mma_f16(O[1][dt], a1, bb);
            }
        }

        __syncthreads();   // all warps done with this stage's smem

        // refill this stage with tile it+2 (or commit an empty group)
        if (it + 2 < N_POS / 64) {
            const int j0 = (it + 2) * 64;
            #pragma unroll
            for (int r = 0; r < 2; r++) {
                int c = tid + r * 256;
                int d = c >> 4, j4 = (c & 15) * 4;
                cp_async16(KsS + d * KS_STR + j4, kb + (long)d * N_POS + j0 + j4);
                cp_async16(VsS + d * VS_STR + j4, vb + (long)d * N_POS + j0 + j4);
            }
        }
        asm volatile("cp.async.commit_group;\n" ::: "memory");
    }

    // ---- reduce l ----
    #pragma unroll
    for (int mt = 0; mt < 2; mt++) {
        l_lo[mt] += __shfl_xor_sync(FULLM, l_lo[mt], 1);
        l_lo[mt] += __shfl_xor_sync(FULLM, l_lo[mt], 2);
        l_hi[mt] += __shfl_xor_sync(FULLM, l_hi[mt], 1);
        l_hi[mt] += __shfl_xor_sync(FULLM, l_hi[mt], 2);
        if (tig == 0) {
            atomicAdd(&sh_l[wq * 32 + mt * 16 + gid],     l_lo[mt]);
            atomicAdd(&sh_l[wq * 32 + mt * 16 + gid + 8], l_hi[mt]);
        }
    }
    __syncthreads();   // l complete; all warps past ring reads

    // ---- merge k-half partials via smem (aliases the K/V ring) ----
    float* Os = SB;                 // [32 d][OS_STR]  (4352 words)
    float* PB = SB + 32 * OS_STR;   // [128 q][PB_STR] (4224 words)

    if (wn == 1) {
        #pragma unroll
        for (int mt = 0; mt < 2; mt++) {
            const int row = wq * 32 + mt * 16 + gid;
            #pragma unroll
            for (int nt = 0; nt < 4; nt++) {
                const int col = nt * 8 + 2 * tig;
                PB[row * PB_STR + col]           = O[mt][nt][0];
                PB[row * PB_STR + col + 1]       = O[mt][nt][1];
                PB[(row + 8) * PB_STR + col]     = O[mt][nt][2];
                PB[(row + 8) * PB_STR + col + 1] = O[mt][nt][3];
            }
        }
    }
    __syncthreads();
    if (wn == 0) {
        #pragma unroll
        for (int mt = 0; mt < 2; mt++) {
            const int row = wq * 32 + mt * 16 + gid;
            const float invl_lo = 1.0f / sh_l[row];
            const float invl_hi = 1.0f / sh_l[row + 8];
            #pragma unroll
            for (int nt = 0; nt < 4; nt++) {
                const int col = nt * 8 + 2 * tig;
                float o0 = (O[mt][nt][0] + PB[row * PB_STR + col])           * invl_lo;
                float o1 = (O[mt][nt][1] + PB[row * PB_STR + col + 1])       * invl_lo;
                float o2 = (O[mt][nt][2] + PB[(row + 8) * PB_STR + col])     * invl_hi;
                float o3 = (O[mt][nt][3] + PB[(row + 8) * PB_STR + col + 1]) * invl_hi;
                Os[col * OS_STR + row]           = o0;
                Os[(col + 1) * OS_STR + row]     = o1;
                Os[col * OS_STR + row + 8]       = o2;
                Os[(col + 1) * OS_STR + row + 8] = o3;
            }
        }
    }
    __syncthreads();

    float* ob = g_att + ((long)b * HID + h * DHEAD) * N_POS + q0;
    #pragma unroll
    for (int r = 0; r < 16; r++) {
        int idx = tid + r * 256;
        int d = idx >> 7, qi = idx & 127;
        ob[(long)d * N_POS + qi] = Os[d * OS_STR + qi];
    }
}

// ---------------------------------------------------------------------------
extern "C" void kernel_launch(void* const* d_in, const int* in_sizes, int n_in,
                              void* d_out, int out_size)
{
    const float* x     = (const float*)d_in[0];   // [4,256,64,64]
    const float* w_qkv = (const float*)d_in[1];   // [384,256]
    const float* w_out = (const float*)d_in[2];   // [256,128]
    const float* b_out = (const float*)d_in[3];   // [256]
    float* y = (float*)d_out;                     // [4,256,64,64]

    // A: qkv = w_qkv @ x   (split-at-staging tf32 MMA + fused q/k L2-norm)
    {
        dim3 grid(N_POS / 64, (3 * HID) / 64, BATCH);
        gemm_qkv_kernel<<<grid, 256>>>(w_qkv, x);
    }
    // B: tensor-core flash attention (all-fp16 MMAs)
    {
        dim3 grid(N_POS / 128, HEADS, BATCH);
        attn_tc_kernel<<<grid, 256>>>();
    }
    // C: y = w_out @ att + b_out   (split-at-staging tf32 MMA)
    {
        dim3 grid(N_POS / 64, C_IN / 64, BATCH);
        gemm_out_kernel<<<grid, 256>>>(w_out, y, b_out);
    }
}

// round 15
// speedup vs baseline: 1.5422x; 1.5422x over previous
#include <cuda_runtime.h>
#include <cstdint>

#define N_POS   4096
#define HEADS   4
#define DHEAD   32
#define C_IN    256
#define HID     128          // HEADS*DHEAD
#define BATCH   4
#define SCALE   10.0f

// Scratch (no cudaMalloc allowed): qkv [b][3*128][n], attn-out [b][128][n]
__device__ float g_qkv[(size_t)BATCH * 3 * HID * N_POS];   // 25.2 MB
__device__ float g_att[(size_t)BATCH * HID * N_POS];       //  8.4 MB

#define FULLM  0xffffffffu

__device__ __forceinline__ uint32_t f2tf(float x) {
    uint32_t r;
    asm("cvt.rna.tf32.f32 %0, %1;" : "=r"(r) : "f"(x));
    return r;
}

// pack two fp32 into half2: lo -> low half, hi -> high half
__device__ __forceinline__ uint32_t pack_h2(float lo, float hi) {
    uint32_t r;
    asm("cvt.rn.f16x2.f32 %0, %1, %2;" : "=r"(r) : "f"(hi), "f"(lo));
    return r;
}

__device__ __forceinline__ void mma_tf32(float d[4], const uint32_t a[4],
                                         const uint32_t b[2]) {
    asm volatile(
        "mma.sync.aligned.m16n8k8.row.col.f32.tf32.tf32.f32 "
        "{%0,%1,%2,%3}, {%4,%5,%6,%7}, {%8,%9}, {%0,%1,%2,%3};"
        : "+f"(d[0]), "+f"(d[1]), "+f"(d[2]), "+f"(d[3])
        : "r"(a[0]), "r"(a[1]), "r"(a[2]), "r"(a[3]), "r"(b[0]), "r"(b[1]));
}

__device__ __forceinline__ void mma_f16(float d[4], const uint32_t a[4],
                                        const uint32_t b[2]) {
    asm volatile(
        "mma.sync.aligned.m16n8k16.row.col.f32.f16.f16.f32 "
        "{%0,%1,%2,%3}, {%4,%5,%6,%7}, {%8,%9}, {%0,%1,%2,%3};"
        : "+f"(d[0]), "+f"(d[1]), "+f"(d[2]), "+f"(d[3])
        : "r"(a[0]), "r"(a[1]), "r"(a[2]), "r"(a[3]), "r"(b[0]), "r"(b[1]));
}

__device__ __forceinline__ void cp_async16(void* smem_dst, const void* gsrc) {
    uint32_t s = (uint32_t)__cvta_generic_to_shared(smem_dst);
    asm volatile("cp.async.cg.shared.global [%0], [%1], 16;\n"
                 :: "r"(s), "l"(gsrc) : "memory");
}

// ---------------------------------------------------------------------------
// Projection GEMM (round-12 measured-best version): tensor-core, 3-term tf32
// split done once at staging into separate hi/lo arrays, register
// double-buffer prefetch, one sync per k-tile. Optional fused L2-norm.
// ---------------------------------------------------------------------------
#define WS_STR 20
#define XS_STR 72

template <bool DO_NORM>
__device__ __forceinline__ void gemm_tc_body(
    const float* __restrict__ W, const float* __restrict__ X,
    float* __restrict__ Y, const float* __restrict__ bias,
    int K, long xstride_b, long ystride_b)
{
    __shared__ uint32_t WsH[2][64 * WS_STR], WsL[2][64 * WS_STR];
    __shared__ uint32_t XsH[2][16 * XS_STR], XsL[2][16 * XS_STR];
    __shared__ float nrm[128];            // [group 0..1][col 0..63]

    const int b  = blockIdx.z;
    const int o0 = blockIdx.y * 64;
    const int i0 = blockIdx.x * 64;
    const float* Xb = X + (long)b * xstride_b;
    float*       Yb = Y + (long)b * ystride_b;

    const int tid  = threadIdx.x;
    const int wid  = tid >> 5;
    const int lane = tid & 31;
    const int gid  = lane >> 2;
    const int tig  = lane & 3;
    const int wq   = wid >> 1;
    const int wn   = wid & 1;

    const int wo = tid >> 2;              // staging: W row (0..63)
    const int wc = (tid & 3) * 4;         // staging: W col group
    const int xc = tid >> 4;              // staging: X row (0..15)
    const int xi = (tid & 15) * 4;        // staging: X col group

    const int KT = K / 16;

    float4 wreg, xreg;

    auto stage_split = [&](int s) {
        uint4 h, l;
        h.x = f2tf(wreg.x); l.x = f2tf(wreg.x - __uint_as_float(h.x));
        h.y = f2tf(wreg.y); l.y = f2tf(wreg.y - __uint_as_float(h.y));
        h.z = f2tf(wreg.z); l.z = f2tf(wreg.z - __uint_as_float(h.z));
        h.w = f2tf(wreg.w); l.w = f2tf(wreg.w - __uint_as_float(h.w));
        *(uint4*)&WsH[s][wo * WS_STR + wc] = h;
        *(uint4*)&WsL[s][wo * WS_STR + wc] = l;
        h.x = f2tf(xreg.x); l.x = f2tf(xreg.x - __uint_as_float(h.x));
        h.y = f2tf(xreg.y); l.y = f2tf(xreg.y - __uint_as_float(h.y));
        h.z = f2tf(xreg.z); l.z = f2tf(xreg.z - __uint_as_float(h.z));
        h.w = f2tf(xreg.w); l.w = f2tf(xreg.w - __uint_as_float(h.w));
        *(uint4*)&XsH[s][xc * XS_STR + xi] = h;
        *(uint4*)&XsL[s][xc * XS_STR + xi] = l;
    };
    auto load_tile = [&](int kt) {
        const int k0 = kt * 16;
        wreg = *(const float4*)&W[(long)(o0 + wo) * K + k0 + wc];
        xreg = *(const float4*)&Xb[(long)(k0 + xc) * N_POS + i0 + xi];
    };

    // prologue: tile 0 staged, tile 1 in regs
    load_tile(0);
    stage_split(0);
    if (KT > 1) load_tile(1);
    if (DO_NORM && tid < 128) nrm[tid] = 0.0f;
    __syncthreads();

    float acc[4][4] = {};

    for (int kt = 0; kt < KT; kt++) {
        const int s = kt & 1;
        if (kt + 1 < KT) {
            stage_split(s ^ 1);               // STS tile kt+1 (regs -> smem)
            if (kt + 2 < KT) load_tile(kt + 2);  // LDG tile kt+2 -> regs
        }

        #pragma unroll
        for (int kk = 0; kk < 2; kk++) {
            const int ar = wq * 16 + gid;
            const int ac = kk * 8 + tig;
            uint32_t aH[4], aL[4];
            aH[0] = WsH[s][ar * WS_STR + ac];
            aH[1] = WsH[s][(ar + 8) * WS_STR + ac];
            aH[2] = WsH[s][ar * WS_STR + ac + 4];
            aH[3] = WsH[s][(ar + 8) * WS_STR + ac + 4];
            aL[0] = WsL[s][ar * WS_STR + ac];
            aL[1] = WsL[s][(ar + 8) * WS_STR + ac];
            aL[2] = WsL[s][ar * WS_STR + ac + 4];
            aL[3] = WsL[s][(ar + 8) * WS_STR + ac + 4];
            #pragma unroll
            for (int nt = 0; nt < 4; nt++) {
                const int col = wn * 32 + nt * 8 + gid;
                const int cr  = kk * 8 + tig;
                uint32_t bH[2], bL[2];
                bH[0] = XsH[s][cr * XS_STR + col];
                bH[1] = XsH[s][(cr + 4) * XS_STR + col];
                bL[0] = XsL[s][cr * XS_STR + col];
                bL[1] = XsL[s][(cr + 4) * XS_STR + col];
                mma_tf32(acc[nt], aH, bH);
                mma_tf32(acc[nt], aH, bL);
                mma_tf32(acc[nt], aL, bH);
            }
        }
        __syncthreads();
    }

    if (DO_NORM && o0 < 2 * HID) {
        // fused L2-norm: sum of squares over each 32-row (d) group, per column
        const int g = wq >> 1;
        float p0[4], p1[4];
        #pragma unroll
        for (int nt = 0; nt < 4; nt++) {
            p0[nt] = acc[nt][0] * acc[nt][0] + acc[nt][2] * acc[nt][2];
            p1[nt] = acc[nt][1] * acc[nt][1] + acc[nt][3] * acc[nt][3];
            #pragma unroll
            for (int m = 4; m < 32; m <<= 1) {
                p0[nt] += __shfl_xor_sync(FULLM, p0[nt], m);
                p1[nt] += __shfl_xor_sync(FULLM, p1[nt], m);
            }
        }
        if (lane < 4) {
            #pragma unroll
            for (int nt = 0; nt < 4; nt++) {
                const int col = wn * 32 + nt * 8 + 2 * tig;
                atomicAdd(&nrm[g * 64 + col],     p0[nt]);
                atomicAdd(&nrm[g * 64 + col + 1], p1[nt]);
            }
        }
        __syncthreads();
        #pragma unroll
        for (int nt = 0; nt < 4; nt++) {
            const int col = wn * 32 + nt * 8 + 2 * tig;
            float i0v = 1.0f / fmaxf(sqrtf(nrm[g * 64 + col]),     1e-12f);
            float i1v = 1.0f / fmaxf(sqrtf(nrm[g * 64 + col + 1]), 1e-12f);
            acc[nt][0] *= i0v; acc[nt][2] *= i0v;
            acc[nt][1] *= i1v; acc[nt][3] *= i1v;
        }
    }

    const int orow = o0 + wq * 16 + gid;
    const float b0 = bias ? bias[orow]     : 0.0f;
    const float b1 = bias ? bias[orow + 8] : 0.0f;
    #pragma unroll
    for (int nt = 0; nt < 4; nt++) {
        const int col = i0 + wn * 32 + nt * 8 + 2 * tig;
        float2 lo, hi;
        lo.x = acc[nt][0] + b0; lo.y = acc[nt][1] + b0;
        hi.x = acc[nt][2] + b1; hi.y = acc[nt][3] + b1;
        *(float2*)&Yb[(long)orow * N_POS + col]       = lo;
        *(float2*)&Yb[(long)(orow + 8) * N_POS + col] = hi;
    }
}

__global__ __launch_bounds__(256) void gemm_qkv_kernel(
    const float* __restrict__ W, const float* __restrict__ X)
{
    gemm_tc_body<true>(W, X, g_qkv, nullptr, C_IN,
                       (long)C_IN * N_POS, (long)3 * HID * N_POS);
}

__global__ __launch_bounds__(256) void gemm_out_kernel(
    const float* __restrict__ W, float* __restrict__ Y,
    const float* __restrict__ bias)
{
    gemm_tc_body<false>(W, g_att, Y, bias, HID,
                        (long)HID * N_POS, (long)C_IN * N_POS);
}

// ---------------------------------------------------------------------------
// Tensor-core flash attention, BOTH GEMMs fp16 m16n8k16 (fp32 accumulate).
//  fp16 mantissa == tf32 mantissa (10 bits) and q,k in [-1,1] -> fp16 QK'
//  has identical precision to the former tf32 path at half the MMA count.
//  Softmax: p = exp(10*s), no shift (p in [e-10, e10], fp16-normal range).
//  GEMM2: S C-frag IS the fp16 A-frag layout -> P packs with cvt only.
//  K/V staged fp32 via 2-stage cp.async ring (wait_group 1, refill at end).
//  KS_STR=68: GEMM1 b-frag banks (8*tig+gid+8*nt) mod 32 conflict-free.
// Block = (b, h, 128-query tile), 8 warps (wq 0..3 x wn 0..1), 512 blocks.
// ---------------------------------------------------------------------------
#define KS_STR 68
#define VS_STR 68
#define OS_STR 136
#define PB_STR 33
#define STG_WORDS (32 * KS_STR + 32 * VS_STR)   // 4352 floats per stage

__global__ __launch_bounds__(256, 2) void attn_tc_kernel()
{
    __shared__ float SB[2 * STG_WORDS];   // K/V ring; aliased by epilogue
    __shared__ float sh_l[128];

    const int b   = blockIdx.z;
    const int h   = blockIdx.y;
    const int q0  = blockIdx.x * 128;
    const int tid = threadIdx.x;
    const int wid  = tid >> 5;
    const int lane = tid & 31;
    const int gid  = lane >> 2;
    const int tig  = lane & 3;
    const int wq   = wid >> 1;   // 0..3 : 32-row q group
    const int wn   = wid & 1;    // 0..1 : j/k half

    const float* qb = g_qkv + ((long)(b * 3 + 0) * HID + h * DHEAD) * N_POS;
    const float* kb = g_qkv + ((long)(b * 3 + 1) * HID + h * DHEAD) * N_POS;
    const float* vb = g_qkv + ((long)(b * 3 + 2) * HID + h * DHEAD) * N_POS;

    float* Ks0 = SB;
    float* Vs0 = SB + 32 * KS_STR;
    float* Ks1 = SB + STG_WORDS;
    float* Vs1 = SB + STG_WORDS + 32 * KS_STR;

    // ---- stage tiles 0 and 1 ----
    #pragma unroll
    for (int r = 0; r < 2; r++) {
        int c = tid + r * 256;
        int d = c >> 4, j4 = (c & 15) * 4;
        cp_async16(Ks0 + d * KS_STR + j4, kb + (long)d * N_POS + j4);
        cp_async16(Vs0 + d * VS_STR + j4, vb + (long)d * N_POS + j4);
    }
    asm volatile("cp.async.commit_group;\n" ::: "memory");
    #pragma unroll
    for (int r = 0; r < 2; r++) {
        int c = tid + r * 256;
        int d = c >> 4, j4 = (c & 15) * 4;
        cp_async16(Ks1 + d * KS_STR + j4, kb + (long)d * N_POS + 64 + j4);
        cp_async16(Vs1 + d * VS_STR + j4, vb + (long)d * N_POS + 64 + j4);
    }
    asm volatile("cp.async.commit_group;\n" ::: "memory");

    // ---- Q fragments in registers as fp16 (one-time) ----
    uint32_t qf[2][2][4];   // [mt][kk2: d-half]
    #pragma unroll
    for (int mt = 0; mt < 2; mt++) {
        const int row = wq * 32 + mt * 16 + gid;
        const float* qp = qb + q0 + row;
        #pragma unroll
        for (int kk2 = 0; kk2 < 2; kk2++) {
            const int d0 = kk2 * 16 + 2 * tig;
            qf[mt][kk2][0] = pack_h2(qp[(long)d0 * N_POS],
                                     qp[(long)(d0 + 1) * N_POS]);
            qf[mt][kk2][1] = pack_h2(qp[(long)d0 * N_POS + 8],
                                     qp[(long)(d0 + 1) * N_POS + 8]);
            qf[mt][kk2][2] = pack_h2(qp[(long)(d0 + 8) * N_POS],
                                     qp[(long)(d0 + 9) * N_POS]);
            qf[mt][kk2][3] = pack_h2(qp[(long)(d0 + 8) * N_POS + 8],
                                     qp[(long)(d0 + 9) * N_POS + 8]);
        }
    }
    if (tid < 128) sh_l[tid] = 0.0f;

    float O[2][4][4] = {};
    float l_lo[2] = {}, l_hi[2] = {};

    for (int it = 0; it < N_POS / 64; it++) {
        const int s = it & 1;
        float* KsS = s ? Ks1 : Ks0;
        float* VsS = s ? Vs1 : Vs0;

        asm volatile("cp.async.wait_group 1;\n" ::: "memory");
        __syncthreads();   // tile it visible to all; also fences Q/sh_l init

        // ---- GEMM1: S[32q x 32j] = Q K'  (fp16 m16n8k16) ----
        float S[2][4][4] = {};
        #pragma unroll
        for (int kk2 = 0; kk2 < 2; kk2++) {
            const int d0 = kk2 * 16 + 2 * tig;
            #pragma unroll
            for (int nt = 0; nt < 4; nt++) {
                const int col = wn * 32 + nt * 8 + gid;
                uint32_t bb[2];
                bb[0] = pack_h2(KsS[(long)d0 * KS_STR + col],
                                KsS[(long)(d0 + 1) * KS_STR + col]);
                bb[1] = pack_h2(KsS[(long)(d0 + 8) * KS_STR + col],
                                KsS[(long)(d0 + 9) * KS_STR + col]);
                mma_f16(S[0][nt], qf[0][kk2], bb);
                mma_f16(S[1][nt], qf[1][kk2], bb);
            }
        }

        // ---- P = exp(10*s) (no shift); accumulate l ----
        #pragma unroll
        for (int mt = 0; mt < 2; mt++)
            #pragma unroll
            for (int nt = 0; nt < 4; nt++) {
                S[mt][nt][0] = __expf(S[mt][nt][0] * SCALE);
                S[mt][nt][1] = __expf(S[mt][nt][1] * SCALE);
                S[mt][nt][2] = __expf(S[mt][nt][2] * SCALE);
                S[mt][nt][3] = __expf(S[mt][nt][3] * SCALE);
                l_lo[mt] += S[mt][nt][0] + S[mt][nt][1];
                l_hi[mt] += S[mt][nt][2] + S[mt][nt][3];
            }

        // ---- GEMM2: O += P V'  (fp16 m16n8k16, no shuffles) ----
        #pragma unroll
        for (int kk2 = 0; kk2 < 2; kk2++) {
            const int g = kk2 * 2;
            uint32_t a0[4], a1[4];
            a0[0] = pack_h2(S[0][g][0],     S[0][g][1]);
            a0[1] = pack_h2(S[0][g][2],     S[0][g][3]);
            a0[2] = pack_h2(S[0][g + 1][0], S[0][g + 1][1]);
            a0[3] = pack_h2(S[0][g + 1][2], S[0][g + 1][3]);
            a1[0] = pack_h2(S[1][g][0],     S[1][g][1]);
            a1[1] = pack_h2(S[1][g][2],     S[1][g][3]);
            a1[2] = pack_h2(S[1][g + 1][0], S[1][g + 1][1]);
            a1[3] = pack_h2(S[1][g + 1][2], S[1][g + 1][3]);
            const int kbase = wn * 32 + kk2 * 16;
            #pragma unroll
            for (int dt = 0; dt < 4; dt++) {
                const int dcol = dt * 8 + gid;
                float2 v0 = *(const float2*)&VsS[dcol * VS_STR + kbase + 2 * tig];
                float2 v1 = *(const float2*)&VsS[dcol * VS_STR + kbase + 2 * tig + 8];
                uint32_t bb[2];
                bb[0] = pack_h2(v0.x, v0.y);
                bb[1] = pack_h2(v1.x, v1.y);
                mma_f16(O[0][dt], a0, bb);
                mma_f16(O[1][dt], a1, bb);
            }
        }

        __syncthreads();   // all warps done with this stage's smem

        // refill this stage with tile it+2 (or commit an empty group)
        if (it + 2 < N_POS / 64) {
            const int j0 = (it + 2) * 64;
            #pragma unroll
            for (int r = 0; r < 2; r++) {
                int c = tid + r * 256;
                int d = c >> 4, j4 = (c & 15) * 4;
                cp_async16(KsS + d * KS_STR + j4, kb + (long)d * N_POS + j0 + j4);
                cp_async16(VsS + d * VS_STR + j4, vb + (long)d * N_POS + j0 + j4);
            }
        }
        asm volatile("cp.async.commit_group;\n" ::: "memory");
    }

    // ---- reduce l ----
    #pragma unroll
    for (int mt = 0; mt < 2; mt++) {
        l_lo[mt] += __shfl_xor_sync(FULLM, l_lo[mt], 1);
        l_lo[mt] += __shfl_xor_sync(FULLM, l_lo[mt], 2);
        l_hi[mt] += __shfl_xor_sync(FULLM, l_hi[mt], 1);
        l_hi[mt] += __shfl_xor_sync(FULLM, l_hi[mt], 2);
        if (tig == 0) {
            atomicAdd(&sh_l[wq * 32 + mt * 16 + gid],     l_lo[mt]);
            atomicAdd(&sh_l[wq * 32 + mt * 16 + gid + 8], l_hi[mt]);
        }
    }
    __syncthreads();   // l complete; all warps past ring reads

    // ---- merge k-half partials via smem (aliases the K/V ring) ----
    float* Os = SB;                 // [32 d][OS_STR]  (4352 words)
    float* PB = SB + 32 * OS_STR;   // [128 q][PB_STR] (4224 words)

    if (wn == 1) {
        #pragma unroll
        for (int mt = 0; mt < 2; mt++) {
            const int row = wq * 32 + mt * 16 + gid;
            #pragma unroll
            for (int nt = 0; nt < 4; nt++) {
                const int col = nt * 8 + 2 * tig;
                PB[row * PB_STR + col]           = O[mt][nt][0];
                PB[row * PB_STR + col + 1]       = O[mt][nt][1];
                PB[(row + 8) * PB_STR + col]     = O[mt][nt][2];
                PB[(row + 8) * PB_STR + col + 1] = O[mt][nt][3];
            }
        }
    }
    __syncthreads();
    if (wn == 0) {
        #pragma unroll
        for (int mt = 0; mt < 2; mt++) {
            const int row = wq * 32 + mt * 16 + gid;
            const float invl_lo = 1.0f / sh_l[row];
            const float invl_hi = 1.0f / sh_l[row + 8];
            #pragma unroll
            for (int nt = 0; nt < 4; nt++) {
                const int col = nt * 8 + 2 * tig;
                float o0 = (O[mt][nt][0] + PB[row * PB_STR + col])           * invl_lo;
                float o1 = (O[mt][nt][1] + PB[row * PB_STR + col + 1])       * invl_lo;
                float o2 = (O[mt][nt][2] + PB[(row + 8) * PB_STR + col])     * invl_hi;
                float o3 = (O[mt][nt][3] + PB[(row + 8) * PB_STR + col + 1]) * invl_hi;
                Os[col * OS_STR + row]           = o0;
                Os[(col + 1) * OS_STR + row]     = o1;
                Os[col * OS_STR + row + 8]       = o2;
                Os[(col + 1) * OS_STR + row + 8] = o3;
            }
        }
    }
    __syncthreads();

    float* ob = g_att + ((long)b * HID + h * DHEAD) * N_POS + q0;
    #pragma unroll
    for (int r = 0; r < 16; r++) {
        int idx = tid + r * 256;
        int d = idx >> 7, qi = idx & 127;
        ob[(long)d * N_POS + qi] = Os[d * OS_STR + qi];
    }
}

// ---------------------------------------------------------------------------
extern "C" void kernel_launch(void* const* d_in, const int* in_sizes, int n_in,
                              void* d_out, int out_size)
{
    const float* x     = (const float*)d_in[0];   // [4,256,64,64]
    const float* w_qkv = (const float*)d_in[1];   // [384,256]
    const float* w_out = (const float*)d_in[2];   // [256,128]
    const float* b_out = (const float*)d_in[3];   // [256]
    float* y = (float*)d_out;                     // [4,256,64,64]

    // A: qkv = w_qkv @ x   (split-at-staging tf32 MMA + fused q/k L2-norm)
    {
        dim3 grid(N_POS / 64, (3 * HID) / 64, BATCH);
        gemm_qkv_kernel<<<grid, 256>>>(w_qkv, x);
    }
    // B: tensor-core flash attention (all-fp16 MMAs)
    {
        dim3 grid(N_POS / 128, HEADS, BATCH);
        attn_tc_kernel<<<grid, 256>>>();
    }
    // C: y = w_out @ att + b_out   (split-at-staging tf32 MMA)
    {
        dim3 grid(N_POS / 64, C_IN / 64, BATCH);
        gemm_out_kernel<<<grid, 256>>>(w_out, y, b_out);
    }
}

// round 16
// speedup vs baseline: 2.0716x; 1.3432x over previous
#include <cuda_runtime.h>
#include <cstdint>

#define N_POS   4096
#define HEADS   4
#define DHEAD   32
#define C_IN    256
#define HID     128          // HEADS*DHEAD
#define BATCH   4
#define SCALE   10.0f
#define FULLM   0xffffffffu

// fp16 scratch (no cudaMalloc allowed)
// q,k: normalized, half2-packed d-pairs: [b][h][d/2][n]   (uint32 = (d_even, d_odd))
// v  : half2-packed n-pairs:             [b][h][d][n/2]   (uint32 = (n_even, n_odd))
__device__ uint32_t g_qh[(size_t)BATCH * HEADS * 16 * N_POS];        // 4.2 MB
__device__ uint32_t g_kh[(size_t)BATCH * HEADS * 16 * N_POS];        // 4.2 MB
__device__ uint32_t g_vh[(size_t)BATCH * HEADS * 32 * (N_POS / 2)];  // 4.2 MB
__device__ float    g_att[(size_t)BATCH * HID * N_POS];              // 8.4 MB

__device__ __forceinline__ uint32_t f2tf(float x) {
    uint32_t r;
    asm("cvt.rna.tf32.f32 %0, %1;" : "=r"(r) : "f"(x));
    return r;
}

// pack two fp32 into half2: first arg -> low half
__device__ __forceinline__ uint32_t pack_h2(float lo, float hi) {
    uint32_t r;
    asm("cvt.rn.f16x2.f32 %0, %1, %2;" : "=r"(r) : "f"(hi), "f"(lo));
    return r;
}

__device__ __forceinline__ void mma_tf32(float d[4], const uint32_t a[4],
                                         const uint32_t b[2]) {
    asm volatile(
        "mma.sync.aligned.m16n8k8.row.col.f32.tf32.tf32.f32 "
        "{%0,%1,%2,%3}, {%4,%5,%6,%7}, {%8,%9}, {%0,%1,%2,%3};"
        : "+f"(d[0]), "+f"(d[1]), "+f"(d[2]), "+f"(d[3])
        : "r"(a[0]), "r"(a[1]), "r"(a[2]), "r"(a[3]), "r"(b[0]), "r"(b[1]));
}

__device__ __forceinline__ void mma_f16(float d[4], const uint32_t a[4],
                                        const uint32_t b[2]) {
    asm volatile(
        "mma.sync.aligned.m16n8k16.row.col.f32.f16.f16.f32 "
        "{%0,%1,%2,%3}, {%4,%5,%6,%7}, {%8,%9}, {%0,%1,%2,%3};"
        : "+f"(d[0]), "+f"(d[1]), "+f"(d[2]), "+f"(d[3])
        : "r"(a[0]), "r"(a[1]), "r"(a[2]), "r"(a[3]), "r"(b[0]), "r"(b[1]));
}

__device__ __forceinline__ void cp_async16(void* smem_dst, const void* gsrc) {
    uint32_t s = (uint32_t)__cvta_generic_to_shared(smem_dst);
    asm volatile("cp.async.cg.shared.global [%0], [%1], 16;\n"
                 :: "r"(s), "l"(gsrc) : "memory");
}
#define CP_COMMIT() asm volatile("cp.async.commit_group;\n" ::: "memory")
#define CP_WAIT1()  asm volatile("cp.async.wait_group 1;\n" ::: "memory")

// ===========================================================================
// Kernel A1: q,k projection — single-pass fp16 m16n8k16 GEMM + fused L2-norm.
// Y rows o0..o0+64 for o0 in {0,64,128,192} (q: <128, k: >=128).
// Staged as half2 c-pairs; register double-buffer prefetch; 1 sync/k-tile.
// Epilogue: shfl_xor(4) pairs adjacent-d lanes -> half2 [d/2][n] store.
// ===========================================================================
#define QW_STR 12    // a-frag banks: (12*gid + tig) mod 32 all distinct
#define QX_STR 72    // b-frag banks: 8*tig + gid distinct

__global__ __launch_bounds__(256) void gemm_qk_kernel(
    const float* __restrict__ W, const float* __restrict__ X)
{
    __shared__ uint32_t Ws2[2][64 * QW_STR];
    __shared__ uint32_t Xs2[2][8 * QX_STR];
    __shared__ float nrm[128];

    const int b  = blockIdx.z;
    const int o0 = blockIdx.y * 64;
    const int i0 = blockIdx.x * 64;
    const float* Xb = X + (long)b * C_IN * N_POS;

    const int tid  = threadIdx.x;
    const int wid  = tid >> 5;
    const int lane = tid & 31;
    const int gid  = lane >> 2;
    const int tig  = lane & 3;
    const int wq   = wid >> 1;
    const int wn   = wid & 1;

    const int so = tid >> 2;          // W staging row 0..63
    const int sc = (tid & 3) * 4;     // c group {0,4,8,12}
    const int sp = tid >> 5;          // X staging c-pair row 0..7
    const int si = (tid & 31) * 2;    // i col (even)

    float4 wreg; float2 xa, xb;
    auto load_tile = [&](int kt) {
        const int k0 = kt * 16;
        wreg = *(const float4*)&W[(long)(o0 + so) * C_IN + k0 + sc];
        xa = *(const float2*)&Xb[(long)(k0 + 2 * sp) * N_POS + i0 + si];
        xb = *(const float2*)&Xb[(long)(k0 + 2 * sp + 1) * N_POS + i0 + si];
    };
    auto stage = [&](int s) {
        uint2 w;
        w.x = pack_h2(wreg.x, wreg.y);      // c-pair (sc, sc+1)
        w.y = pack_h2(wreg.z, wreg.w);      // c-pair (sc+2, sc+3)
        *(uint2*)&Ws2[s][so * QW_STR + (sc >> 1)] = w;
        uint2 xx;
        xx.x = pack_h2(xa.x, xb.x);         // c-pair at col si
        xx.y = pack_h2(xa.y, xb.y);         // c-pair at col si+1
        *(uint2*)&Xs2[s][sp * QX_STR + si] = xx;
    };

    load_tile(0);
    stage(0);
    load_tile(1);
    if (tid < 128) nrm[tid] = 0.0f;
    __syncthreads();

    float acc[4][4] = {};
    const int KT = C_IN / 16;   // 16

    for (int kt = 0; kt < KT; kt++) {
        const int s = kt & 1;
        if (kt + 1 < KT) {
            stage(s ^ 1);
            if (kt + 2 < KT) load_tile(kt + 2);
        }
        const int ar = wq * 16 + gid;
        uint32_t a[4];
        a[0] = Ws2[s][ar * QW_STR + tig];
        a[1] = Ws2[s][(ar + 8) * QW_STR + tig];
        a[2] = Ws2[s][ar * QW_STR + tig + 4];
        a[3] = Ws2[s][(ar + 8) * QW_STR + tig + 4];
        #pragma unroll
        for (int nt = 0; nt < 4; nt++) {
            const int col = wn * 32 + nt * 8 + gid;
            uint32_t bb[2];
            bb[0] = Xs2[s][tig * QX_STR + col];
            bb[1] = Xs2[s][(tig + 4) * QX_STR + col];
            mma_f16(acc[nt], a, bb);
        }
        __syncthreads();
    }

    // ---- fused L2-norm over 32-row (d) groups, per column ----
    {
        const int g = wq >> 1;
        float p0[4], p1[4];
        #pragma unroll
        for (int nt = 0; nt < 4; nt++) {
            p0[nt] = acc[nt][0] * acc[nt][0] + acc[nt][2] * acc[nt][2];
            p1[nt] = acc[nt][1] * acc[nt][1] + acc[nt][3] * acc[nt][3];
            #pragma unroll
            for (int m = 4; m < 32; m <<= 1) {
                p0[nt] += __shfl_xor_sync(FULLM, p0[nt], m);
                p1[nt] += __shfl_xor_sync(FULLM, p1[nt], m);
            }
        }
        if (lane < 4) {
            #pragma unroll
            for (int nt = 0; nt < 4; nt++) {
                const int col = wn * 32 + nt * 8 + 2 * tig;
                atomicAdd(&nrm[g * 64 + col],     p0[nt]);
                atomicAdd(&nrm[g * 64 + col + 1], p1[nt]);
            }
        }
        __syncthreads();
        #pragma unroll
        for (int nt = 0; nt < 4; nt++) {
            const int col = wn * 32 + nt * 8 + 2 * tig;
            float i0v = 1.0f / fmaxf(sqrtf(nrm[g * 64 + col]),     1e-12f);
            float i1v = 1.0f / fmaxf(sqrtf(nrm[g * 64 + col + 1]), 1e-12f);
            acc[nt][0] *= i0v; acc[nt][2] *= i0v;
            acc[nt][1] *= i1v; acc[nt][3] *= i1v;
        }
    }

    // ---- epilogue: pack adjacent-d pairs via shfl, store half2 [d/2][n] ----
    const int sec = o0 >> 7;                   // 0 = q, 1 = k
    uint32_t* dstb = sec ? g_kh : g_qh;
    const int r  = o0 + wq * 16 + gid;
    const int lr = r - sec * 128;
    const int h  = lr >> 5, d = lr & 31;
    uint32_t* dst = dstb + (long)(b * HEADS + h) * 16 * N_POS;

    #pragma unroll
    for (int nt = 0; nt < 4; nt++) {
        const int c = i0 + wn * 32 + nt * 8 + 2 * tig;
        float p0 = __shfl_xor_sync(FULLM, acc[nt][0], 4);
        float p1 = __shfl_xor_sync(FULLM, acc[nt][1], 4);
        float p2 = __shfl_xor_sync(FULLM, acc[nt][2], 4);
        float p3 = __shfl_xor_sync(FULLM, acc[nt][3], 4);
        if ((gid & 1) == 0) {      // own row = d even, partner = d+1
            uint2 lo, hi;
            lo.x = pack_h2(acc[nt][0], p0);    // (d, d+1) at col c
            lo.y = pack_h2(acc[nt][1], p1);    // at col c+1
            hi.x = pack_h2(acc[nt][2], p2);    // (d+8, d+9) at c
            hi.y = pack_h2(acc[nt][3], p3);
            *(uint2*)&dst[(long)(d >> 1) * N_POS + c]           = lo;
            *(uint2*)&dst[(long)((d + 8) >> 1) * N_POS + c]     = hi;
        }
    }
}

// ===========================================================================
// Tensor-core 3-term tf32 GEMM body (round-12/15 proven version).
// MODE 0: plain fp32 store + bias (out-proj).  MODE 1: v half2 store to g_vh.
// ===========================================================================
#define WS_STR 20
#define XS_STR 72

template <int MODE>
__device__ __forceinline__ void gemm_tc_body(
    const float* __restrict__ W, const float* __restrict__ X,
    float* __restrict__ Y, const float* __restrict__ bias,
    int K, long xstride_b, long ystride_b)
{
    __shared__ uint32_t WsH[2][64 * WS_STR], WsL[2][64 * WS_STR];
    __shared__ uint32_t XsH[2][16 * XS_STR], XsL[2][16 * XS_STR];

    const int b  = blockIdx.z;
    const int o0 = blockIdx.y * 64;
    const int i0 = blockIdx.x * 64;
    const float* Xb = X + (long)b * xstride_b;
    float*       Yb = Y ? (Y + (long)b * ystride_b) : nullptr;

    const int tid  = threadIdx.x;
    const int wid  = tid >> 5;
    const int lane = tid & 31;
    const int gid  = lane >> 2;
    const int tig  = lane & 3;
    const int wq   = wid >> 1;
    const int wn   = wid & 1;

    const int wo = tid >> 2;
    const int wc = (tid & 3) * 4;
    const int xc = tid >> 4;
    const int xi = (tid & 15) * 4;

    const int KT = K / 16;
    float4 wreg, xreg;

    auto stage_split = [&](int s) {
        uint4 hh, ll;
        hh.x = f2tf(wreg.x); ll.x = f2tf(wreg.x - __uint_as_float(hh.x));
        hh.y = f2tf(wreg.y); ll.y = f2tf(wreg.y - __uint_as_float(hh.y));
        hh.z = f2tf(wreg.z); ll.z = f2tf(wreg.z - __uint_as_float(hh.z));
        hh.w = f2tf(wreg.w); ll.w = f2tf(wreg.w - __uint_as_float(hh.w));
        *(uint4*)&WsH[s][wo * WS_STR + wc] = hh;
        *(uint4*)&WsL[s][wo * WS_STR + wc] = ll;
        hh.x = f2tf(xreg.x); ll.x = f2tf(xreg.x - __uint_as_float(hh.x));
        hh.y = f2tf(xreg.y); ll.y = f2tf(xreg.y - __uint_as_float(hh.y));
        hh.z = f2tf(xreg.z); ll.z = f2tf(xreg.z - __uint_as_float(hh.z));
        hh.w = f2tf(xreg.w); ll.w = f2tf(xreg.w - __uint_as_float(hh.w));
        *(uint4*)&XsH[s][xc * XS_STR + xi] = hh;
        *(uint4*)&XsL[s][xc * XS_STR + xi] = ll;
    };
    auto load_tile = [&](int kt) {
        const int k0 = kt * 16;
        wreg = *(const float4*)&W[(long)(o0 + wo) * K + k0 + wc];
        xreg = *(const float4*)&Xb[(long)(k0 + xc) * N_POS + i0 + xi];
    };

    load_tile(0);
    stage_split(0);
    if (KT > 1) load_tile(1);
    __syncthreads();

    float acc[4][4] = {};

    for (int kt = 0; kt < KT; kt++) {
        const int s = kt & 1;
        if (kt + 1 < KT) {
            stage_split(s ^ 1);
            if (kt + 2 < KT) load_tile(kt + 2);
        }
        #pragma unroll
        for (int kk = 0; kk < 2; kk++) {
            const int ar = wq * 16 + gid;
            const int ac = kk * 8 + tig;
            uint32_t aH[4], aL[4];
            aH[0] = WsH[s][ar * WS_STR + ac];
            aH[1] = WsH[s][(ar + 8) * WS_STR + ac];
            aH[2] = WsH[s][ar * WS_STR + ac + 4];
            aH[3] = WsH[s][(ar + 8) * WS_STR + ac + 4];
            aL[0] = WsL[s][ar * WS_STR + ac];
            aL[1] = WsL[s][(ar + 8) * WS_STR + ac];
            aL[2] = WsL[s][ar * WS_STR + ac + 4];
            aL[3] = WsL[s][(ar + 8) * WS_STR + ac + 4];
            #pragma unroll
            for (int nt = 0; nt < 4; nt++) {
                const int col = wn * 32 + nt * 8 + gid;
                const int cr  = kk * 8 + tig;
                uint32_t bH[2], bL[2];
                bH[0] = XsH[s][cr * XS_STR + col];
                bH[1] = XsH[s][(cr + 4) * XS_STR + col];
                bL[0] = XsL[s][cr * XS_STR + col];
                bL[1] = XsL[s][(cr + 4) * XS_STR + col];
                mma_tf32(acc[nt], aH, bH);
                mma_tf32(acc[nt], aH, bL);
                mma_tf32(acc[nt], aL, bH);
            }
        }
        __syncthreads();
    }

    if (MODE == 0) {
        const int orow = o0 + wq * 16 + gid;
        const float b0 = bias ? bias[orow]     : 0.0f;
        const float b1 = bias ? bias[orow + 8] : 0.0f;
        #pragma unroll
        for (int nt = 0; nt < 4; nt++) {
            const int col = i0 + wn * 32 + nt * 8 + 2 * tig;
            float2 lo, hi;
            lo.x = acc[nt][0] + b0; lo.y = acc[nt][1] + b0;
            hi.x = acc[nt][2] + b1; hi.y = acc[nt][3] + b1;
            *(float2*)&Yb[(long)orow * N_POS + col]       = lo;
            *(float2*)&Yb[(long)(orow + 8) * N_POS + col] = hi;
        }
    } else {
        // v store: half2 n-pairs to g_vh [b][h][d][n/2]
        const int lr = o0 + wq * 16 + gid;   // local v channel (W pre-offset)
        const int h  = lr >> 5, d = lr & 31;
        uint32_t* dst = g_vh + (long)(b * HEADS + h) * 32 * (N_POS / 2);
        #pragma unroll
        for (int nt = 0; nt < 4; nt++) {
            const int c = i0 + wn * 32 + nt * 8 + 2 * tig;
            dst[(long)d * (N_POS / 2) + (c >> 1)]       = pack_h2(acc[nt][0], acc[nt][1]);
            dst[(long)(d + 8) * (N_POS / 2) + (c >> 1)] = pack_h2(acc[nt][2], acc[nt][3]);
        }
    }
}

__global__ __launch_bounds__(256) void gemm_v_kernel(
    const float* __restrict__ W, const float* __restrict__ X)
{
    gemm_tc_body<1>(W, X, nullptr, nullptr, C_IN,
                    (long)C_IN * N_POS, 0);
}

__global__ __launch_bounds__(256) void gemm_out_kernel(
    const float* __restrict__ W, float* __restrict__ Y,
    const float* __restrict__ bias)
{
    gemm_tc_body<0>(W, g_att, Y, bias, HID,
                    (long)HID * N_POS, (long)C_IN * N_POS);
}

// ===========================================================================
// Tensor-core flash attention, all-fp16 MMAs, pre-packed fp16 inputs.
//  K tile: 16 half2-rows (d-pairs) x 64 j -> b-frag = ONE LDS.32, no cvt.
//  V tile: 32 d-rows x 32 half2-cols (j-pairs) -> b-frag = ONE LDS.32.
//  Q frags: one LDG.32 each (pre-packed, pre-normalized).
//  Softmax: p = exp(10*s), no shift; P packs via cvt only (C-frag == A-frag).
//  2-stage cp.async ring (wait_group 1, refill at end), 2 syncs/iter.
// Block = (b, h, 128-query tile), 8 warps (wq 0..3 x wn 0..1), 512 blocks.
// ===========================================================================
#define AK_STR 72    // banks: 8*tig + gid (+8nt) -> conflict-free
#define AV_STR 36    // banks: 4*gid + tig (+const) -> conflict-free
#define AST_W  (16 * AK_STR + 32 * AV_STR)   // 2304 words per stage
#define OS_STR 136
#define PB_STR 33

__global__ __launch_bounds__(256, 2) void attn_tc_kernel()
{
    __shared__ uint32_t SB[32 * OS_STR + 128 * PB_STR];  // 8576 >= 2*AST_W
    __shared__ float sh_l[128];

    const int b   = blockIdx.z;
    const int h   = blockIdx.y;
    const int q0  = blockIdx.x * 128;
    const int tid = threadIdx.x;
    const int wid  = tid >> 5;
    const int lane = tid & 31;
    const int gid  = lane >> 2;
    const int tig  = lane & 3;
    const int wq   = wid >> 1;
    const int wn   = wid & 1;

    const uint32_t* qh = g_qh + (long)(b * HEADS + h) * 16 * N_POS;
    const uint32_t* kh = g_kh + (long)(b * HEADS + h) * 16 * N_POS;
    const uint32_t* vh = g_vh + (long)(b * HEADS + h) * 32 * (N_POS / 2);

    uint32_t* Ks0 = SB;
    uint32_t* Vs0 = SB + 16 * AK_STR;
    uint32_t* Ks1 = SB + AST_W;
    uint32_t* Vs1 = SB + AST_W + 16 * AK_STR;

    const int kr = tid >> 4;           // K staging row 0..15
    const int kc = (tid & 15) * 4;     // K staging col
    const int vr = tid >> 3;           // V staging row 0..31
    const int vc = (tid & 7) * 4;      // V staging col (half2 units)

    // stage tiles 0 and 1
    cp_async16(Ks0 + kr * AK_STR + kc, kh + (long)kr * N_POS + kc);
    cp_async16(Vs0 + vr * AV_STR + vc, vh + (long)vr * (N_POS / 2) + vc);
    CP_COMMIT();
    cp_async16(Ks1 + kr * AK_STR + kc, kh + (long)kr * N_POS + 64 + kc);
    cp_async16(Vs1 + vr * AV_STR + vc, vh + (long)vr * (N_POS / 2) + 32 + vc);
    CP_COMMIT();

    // Q fragments: one LDG.32 each (pre-packed d-pairs)
    uint32_t qf[2][2][4];
    #pragma unroll
    for (int mt = 0; mt < 2; mt++) {
        const int row = q0 + wq * 32 + mt * 16 + gid;
        #pragma unroll
        for (int kk2 = 0; kk2 < 2; kk2++) {
            qf[mt][kk2][0] = qh[(long)(kk2 * 8 + tig) * N_POS + row];
            qf[mt][kk2][1] = qh[(long)(kk2 * 8 + tig) * N_POS + row + 8];
            qf[mt][kk2][2] = qh[(long)(kk2 * 8 + tig + 4) * N_POS + row];
            qf[mt][kk2][3] = qh[(long)(kk2 * 8 + tig + 4) * N_POS + row + 8];
        }
    }
    if (tid < 128) sh_l[tid] = 0.0f;

    float O[2][4][4] = {};
    float l_lo[2] = {}, l_hi[2] = {};

    for (int it = 0; it < N_POS / 64; it++) {
        const int s = it & 1;
        uint32_t* KsS = s ? Ks1 : Ks0;
        uint32_t* VsS = s ? Vs1 : Vs0;

        CP_WAIT1();
        __syncthreads();   // tile it visible; also fences Q/sh_l init

        // ---- GEMM1: S[32q x 32j] = Q K' ----
        float S[2][4][4] = {};
        #pragma unroll
        for (int kk2 = 0; kk2 < 2; kk2++) {
            #pragma unroll
            for (int nt = 0; nt < 4; nt++) {
                const int col = wn * 32 + nt * 8 + gid;
                uint32_t bb[2];
                bb[0] = KsS[(kk2 * 8 + tig) * AK_STR + col];
                bb[1] = KsS[(kk2 * 8 + tig + 4) * AK_STR + col];
                mma_f16(S[0][nt], qf[0][kk2], bb);
                mma_f16(S[1][nt], qf[1][kk2], bb);
            }
        }

        // ---- P = exp(10*s); accumulate l ----
        #pragma unroll
        for (int mt = 0; mt < 2; mt++)
            #pragma unroll
            for (int nt = 0; nt < 4; nt++) {
                S[mt][nt][0] = __expf(S[mt][nt][0] * SCALE);
                S[mt][nt][1] = __expf(S[mt][nt][1] * SCALE);
                S[mt][nt][2] = __expf(S[mt][nt][2] * SCALE);
                S[mt][nt][3] = __expf(S[mt][nt][3] * SCALE);
                l_lo[mt] += S[mt][nt][0] + S[mt][nt][1];
                l_hi[mt] += S[mt][nt][2] + S[mt][nt][3];
            }

        // ---- GEMM2: O += P V' ----
        #pragma unroll
        for (int kk2 = 0; kk2 < 2; kk2++) {
            const int g = kk2 * 2;
            uint32_t a0[4], a1[4];
            a0[0] = pack_h2(S[0][g][0],     S[0][g][1]);
            a0[1] = pack_h2(S[0][g][2],     S[0][g][3]);
            a0[2] = pack_h2(S[0][g + 1][0], S[0][g + 1][1]);
            a0[3] = pack_h2(S[0][g + 1][2], S[0][g + 1][3]);
            a1[0] = pack_h2(S[1][g][0],     S[1][g][1]);
            a1[1] = pack_h2(S[1][g][2],     S[1][g][3]);
            a1[2] = pack_h2(S[1][g + 1][0], S[1][g + 1][1]);
            a1[3] = pack_h2(S[1][g + 1][2], S[1][g + 1][3]);
            const int kb2 = wn * 16 + kk2 * 8;   // j-pair base
            #pragma unroll
            for (int dt = 0; dt < 4; dt++) {
                const int dcol = dt * 8 + gid;
                uint32_t bb[2];
                bb[0] = VsS[dcol * AV_STR + kb2 + tig];
                bb[1] = VsS[dcol * AV_STR + kb2 + tig + 4];
                mma_f16(O[0][dt], a0, bb);
                mma_f16(O[1][dt], a1, bb);
            }
        }

        __syncthreads();   // all warps done with this stage's smem

        if (it + 2 < N_POS / 64) {
            const int j0 = (it + 2) * 64;
            cp_async16(KsS + kr * AK_STR + kc, kh + (long)kr * N_POS + j0 + kc);
            cp_async16(VsS + vr * AV_STR + vc,
                       vh + (long)vr * (N_POS / 2) + j0 / 2 + vc);
        }
        CP_COMMIT();
    }

    // ---- reduce l ----
    #pragma unroll
    for (int mt = 0; mt < 2; mt++) {
        l_lo[mt] += __shfl_xor_sync(FULLM, l_lo[mt], 1);
        l_lo[mt] += __shfl_xor_sync(FULLM, l_lo[mt], 2);
        l_hi[mt] += __shfl_xor_sync(FULLM, l_hi[mt], 1);
        l_hi[mt] += __shfl_xor_sync(FULLM, l_hi[mt], 2);
        if (tig == 0) {
            atomicAdd(&sh_l[wq * 32 + mt * 16 + gid],     l_lo[mt]);
            atomicAdd(&sh_l[wq * 32 + mt * 16 + gid + 8], l_hi[mt]);
        }
    }
    __syncthreads();

    // ---- merge k-half partials via smem (aliases the ring) ----
    float* Os = (float*)SB;                  // [32 d][OS_STR]
    float* PB = (float*)SB + 32 * OS_STR;    // [128 q][PB_STR]

    if (wn == 1) {
        #pragma unroll
        for (int mt = 0; mt < 2; mt++) {
            const int row = wq * 32 + mt * 16 + gid;
            #pragma unroll
            for (int nt = 0; nt < 4; nt++) {
                const int col = nt * 8 + 2 * tig;
                PB[row * PB_STR + col]           = O[mt][nt][0];
                PB[row * PB_STR + col + 1]       = O[mt][nt][1];
                PB[(row + 8) * PB_STR + col]     = O[mt][nt][2];
                PB[(row + 8) * PB_STR + col + 1] = O[mt][nt][3];
            }
        }
    }
    __syncthreads();
    if (wn == 0) {
        #pragma unroll
        for (int mt = 0; mt < 2; mt++) {
            const int row = wq * 32 + mt * 16 + gid;
            const float invl_lo = 1.0f / sh_l[row];
            const float invl_hi = 1.0f / sh_l[row + 8];
            #pragma unroll
            for (int nt = 0; nt < 4; nt++) {
                const int col = nt * 8 + 2 * tig;
                float o0 = (O[mt][nt][0] + PB[row * PB_STR + col])           * invl_lo;
                float o1 = (O[mt][nt][1] + PB[row * PB_STR + col + 1])       * invl_lo;
                float o2 = (O[mt][nt][2] + PB[(row + 8) * PB_STR + col])     * invl_hi;
                float o3 = (O[mt][nt][3] + PB[(row + 8) * PB_STR + col + 1]) * invl_hi;
                Os[col * OS_STR + row]           = o0;
                Os[(col + 1) * OS_STR + row]     = o1;
                Os[col * OS_STR + row + 8]       = o2;
                Os[(col + 1) * OS_STR + row + 8] = o3;
            }
        }
    }
    __syncthreads();

    float* ob = g_att + ((long)b * HID + h * DHEAD) * N_POS + q0;
    #pragma unroll
    for (int r = 0; r < 16; r++) {
        int idx = tid + r * 256;
        int d = idx >> 7, qi = idx & 127;
        ob[(long)d * N_POS + qi] = Os[d * OS_STR + qi];
    }
}

// ---------------------------------------------------------------------------
extern "C" void kernel_launch(void* const* d_in, const int* in_sizes, int n_in,
                              void* d_out, int out_size)
{
    const float* x     = (const float*)d_in[0];   // [4,256,64,64]
    const float* w_qkv = (const float*)d_in[1];   // [384,256]
    const float* w_out = (const float*)d_in[2];   // [256,128]
    const float* b_out = (const float*)d_in[3];   // [256]
    float* y = (float*)d_out;                     // [4,256,64,64]

    // A1: q,k = norm(w_qkv[0:256] @ x)  (fp16 single GEMM, packed fp16 out)
    {
        dim3 grid(N_POS / 64, 4, BATCH);
        gemm_qk_kernel<<<grid, 256>>>(w_qkv, x);
    }
    // A2: v = w_qkv[256:384] @ x  (3-term tf32 GEMM, packed fp16 out)
    {
        dim3 grid(N_POS / 64, 2, BATCH);
        gemm_v_kernel<<<grid, 256>>>(w_qkv + 256 * C_IN, x);
    }
    // B: flash attention (all-fp16 MMAs, pre-packed inputs)
    {
        dim3 grid(N_POS / 128, HEADS, BATCH);
        attn_tc_kernel<<<grid, 256>>>();
    }
    // C: y = w_out @ att + b_out  (3-term tf32)
    {
        dim3 grid(N_POS / 64, C_IN / 64, BATCH);
        gemm_out_kernel<<<grid, 256>>>(w_out, y, b_out);
    }
}